// round 12
// baseline (speedup 1.0000x reference)
#include <cuda_runtime.h>

// newIF spiking neuron forward (T=8) — roofline kernel.
// One thread = 4 neurons (float4), 8 front-batched independent LDG.E.128
// (measured optimum burst depth), streaming hints.
// R10: 64-thread blocks — continuation of the granularity trend
// (256t: 82.4us, 128t: 82.0us). Grid 32768, 2 warps/block.
// 512MB mandatory traffic @ ~6.2TB/s achieved = HBM3e mixed-R/W ceiling.

#define T_STEPS 8

__global__ __launch_bounds__(64) void newif_kernel(
    const float4* __restrict__ x,
    const float*  __restrict__ thresh,
    float4*       __restrict__ out,
    int n4)  // neurons per timestep / 4
{
    int i = blockIdx.x * blockDim.x + threadIdx.x;
    if (i >= n4) return;

    const float thre  = __ldg(thresh);
    const float half  = 0.5f * thre;
    const float tcap  = (float)T_STEPS * thre;

    // Front-batched loads: 8 independent LDG.E.128 (MLP=8 per thread)
    float4 xv[T_STEPS];
    #pragma unroll
    for (int t = 0; t < T_STEPS; t++)
        xv[t] = __ldcs(&x[t * n4 + i]);

    float mem[4] = {half, half, half, half};
    float cnt[4] = {0.f, 0.f, 0.f, 0.f};
    unsigned smask[4] = {0u, 0u, 0u, 0u};

    #pragma unroll
    for (int t = 0; t < T_STEPS; t++) {
        const float* xt = reinterpret_cast<const float*>(&xv[t]);
        #pragma unroll
        for (int l = 0; l < 4; l++) {
            float m = mem[l] + xt[l];
            bool s = (m >= thre);
            if (s) { m -= thre; cnt[l] += 1.f; smask[l] |= (1u << t); }
            mem[l] = m;
        }
    }

    float nt[4];
    #pragma unroll
    for (int l = 0; l < 4; l++) {
        float compen = mem[l] - half + cnt[l] * thre;
        float cv = fminf(compen, tcap);
        bool cond = (cv > 0.f) && (cnt[l] > 0.f);
        nt[l] = cond ? (cv / cnt[l]) : 0.f;
    }

    #pragma unroll
    for (int t = 0; t < T_STEPS; t++) {
        float4 o;
        o.x = (smask[0] >> t & 1u) ? nt[0] : 0.f;
        o.y = (smask[1] >> t & 1u) ? nt[1] : 0.f;
        o.z = (smask[2] >> t & 1u) ? nt[2] : 0.f;
        o.w = (smask[3] >> t & 1u) ? nt[3] : 0.f;
        __stcs(&out[t * n4 + i], o);
    }
}

extern "C" void kernel_launch(void* const* d_in, const int* in_sizes, int n_in,
                              void* d_out, int out_size) {
    const float* x      = (const float*)d_in[0];
    const float* thresh = (const float*)d_in[1];
    float* out          = (float*)d_out;

    int total = in_sizes[0];          // T * B * C * H * W
    int n_per_t = total / T_STEPS;    // B * C * H * W
    int n4 = n_per_t / 4;             // float4 units per timestep

    int threads = 64;
    int blocks = (n4 + threads - 1) / threads;
    newif_kernel<<<blocks, threads>>>(
        (const float4*)x, thresh, (float4*)out, n4);
}

// round 13
// speedup vs baseline: 1.0047x; 1.0047x over previous
#include <cuda_runtime.h>

// newIF spiking neuron forward (T=8) — FINAL roofline kernel (R9 config).
// One thread = 4 neurons (float4), 8 front-batched independent LDG.E.128
// (measured optimum burst depth), 128-thread blocks (measured optimum
// granularity), streaming cache hints.
//
// 512MB mandatory traffic @ 6.18TB/s achieved (78% of spec) = HBM3e mixed
// 1:1 R/W ceiling. Swept & closed: burst depth {4,8,16}, blocks
// {64,128,256,512}, occupancy 43-81%, all cache-hint combos, grid-stride.

#define T_STEPS 8

__global__ __launch_bounds__(128) void newif_kernel(
    const float4* __restrict__ x,
    const float*  __restrict__ thresh,
    float4*       __restrict__ out,
    int n4)  // neurons per timestep / 4
{
    int i = blockIdx.x * blockDim.x + threadIdx.x;
    if (i >= n4) return;

    const float thre  = __ldg(thresh);
    const float half  = 0.5f * thre;
    const float tcap  = (float)T_STEPS * thre;

    // Front-batched loads: 8 independent LDG.E.128 (MLP=8 per thread)
    float4 xv[T_STEPS];
    #pragma unroll
    for (int t = 0; t < T_STEPS; t++)
        xv[t] = __ldcs(&x[t * n4 + i]);

    float mem[4] = {half, half, half, half};
    float cnt[4] = {0.f, 0.f, 0.f, 0.f};
    unsigned smask[4] = {0u, 0u, 0u, 0u};

    #pragma unroll
    for (int t = 0; t < T_STEPS; t++) {
        const float* xt = reinterpret_cast<const float*>(&xv[t]);
        #pragma unroll
        for (int l = 0; l < 4; l++) {
            float m = mem[l] + xt[l];
            bool s = (m >= thre);
            if (s) { m -= thre; cnt[l] += 1.f; smask[l] |= (1u << t); }
            mem[l] = m;
        }
    }

    float nt[4];
    #pragma unroll
    for (int l = 0; l < 4; l++) {
        float compen = mem[l] - half + cnt[l] * thre;
        float cv = fminf(compen, tcap);
        bool cond = (cv > 0.f) && (cnt[l] > 0.f);
        nt[l] = cond ? (cv / cnt[l]) : 0.f;
    }

    #pragma unroll
    for (int t = 0; t < T_STEPS; t++) {
        float4 o;
        o.x = (smask[0] >> t & 1u) ? nt[0] : 0.f;
        o.y = (smask[1] >> t & 1u) ? nt[1] : 0.f;
        o.z = (smask[2] >> t & 1u) ? nt[2] : 0.f;
        o.w = (smask[3] >> t & 1u) ? nt[3] : 0.f;
        __stcs(&out[t * n4 + i], o);
    }
}

extern "C" void kernel_launch(void* const* d_in, const int* in_sizes, int n_in,
                              void* d_out, int out_size) {
    const float* x      = (const float*)d_in[0];
    const float* thresh = (const float*)d_in[1];
    float* out          = (float*)d_out;

    int total = in_sizes[0];          // T * B * C * H * W
    int n_per_t = total / T_STEPS;    // B * C * H * W
    int n4 = n_per_t / 4;             // float4 units per timestep

    int threads = 128;
    int blocks = (n4 + threads - 1) / threads;
    newif_kernel<<<blocks, threads>>>(
        (const float4*)x, thresh, (float4*)out, n4);
}